// round 4
// baseline (speedup 1.0000x reference)
#include <cuda_runtime.h>

#define N_SAMPLES 16384
#define DIM       1024
#define MARGIN    1.0f
#define EPSF      1e-6f
#define BLOCK     256   // 256 threads * float4 = 1024 floats = one row
#define GRID      2048  // each block loops over N_SAMPLES/GRID = 8 samples

__device__ double g_acc;      // zero-initialized at load; reset by last block each call
__device__ unsigned g_count;  // ditto

__global__ __launch_bounds__(BLOCK)
void cl_fused_kernel(const float* __restrict__ emb,
                     const int* __restrict__ pos_idx,
                     const int* __restrict__ neg_idx,
                     float* __restrict__ out)
{
    const int t = threadIdx.x;
    const int warp = t >> 5;
    const int lane = t & 31;

    __shared__ float sm[3][BLOCK / 32];

    double local = 0.0;   // only meaningful on t==0

    for (int i = blockIdx.x; i < N_SAMPLES; i += GRID) {
        const int p = pos_idx[i];
        const int n = neg_idx[i];

        const float4* ra = (const float4*)(emb + (size_t)i * DIM);
        const float4* rb = (const float4*)(emb + (size_t)p * DIM);
        const float4* rc = (const float4*)(emb + (size_t)n * DIM);

        float4 a = ra[t];
        float4 b = rb[t];
        float4 c = rc[t];

        // --- phase 1: per-row sum of squares (norms) ---
        float sa = a.x*a.x + a.y*a.y + a.z*a.z + a.w*a.w;
        float sb = b.x*b.x + b.y*b.y + b.z*b.z + b.w*b.w;
        float sc = c.x*c.x + c.y*c.y + c.z*c.z + c.w*c.w;

        #pragma unroll
        for (int o = 16; o > 0; o >>= 1) {
            sa += __shfl_xor_sync(0xffffffffu, sa, o);
            sb += __shfl_xor_sync(0xffffffffu, sb, o);
            sc += __shfl_xor_sync(0xffffffffu, sc, o);
        }

        __syncthreads();  // protect sm reuse across loop iterations
        if (lane == 0) { sm[0][warp] = sa; sm[1][warp] = sb; sm[2][warp] = sc; }
        __syncthreads();

        float ssa = 0.f, ssb = 0.f, ssc = 0.f;
        #pragma unroll
        for (int w = 0; w < BLOCK / 32; w++) {
            ssa += sm[0][w];
            ssb += sm[1][w];
            ssc += sm[2][w];
        }
        const float ia = 1.0f / fmaxf(sqrtf(ssa), EPSF);
        const float ib = 1.0f / fmaxf(sqrtf(ssb), EPSF);
        const float ic = 1.0f / fmaxf(sqrtf(ssc), EPSF);

        // --- phase 2: squared "pairwise distance" sums (+eps inside) ---
        float dp = 0.f, dn = 0.f;
        {
            float d;
            d = a.x*ia - b.x*ib + EPSF; dp += d*d;
            d = a.y*ia - b.y*ib + EPSF; dp += d*d;
            d = a.z*ia - b.z*ib + EPSF; dp += d*d;
            d = a.w*ia - b.w*ib + EPSF; dp += d*d;

            d = a.x*ia - c.x*ic + EPSF; dn += d*d;
            d = a.y*ia - c.y*ic + EPSF; dn += d*d;
            d = a.z*ia - c.z*ic + EPSF; dn += d*d;
            d = a.w*ia - c.w*ic + EPSF; dn += d*d;
        }

        #pragma unroll
        for (int o = 16; o > 0; o >>= 1) {
            dp += __shfl_xor_sync(0xffffffffu, dp, o);
            dn += __shfl_xor_sync(0xffffffffu, dn, o);
        }

        __syncthreads();  // phase-1 sm reads done
        if (lane == 0) { sm[0][warp] = dp; sm[1][warp] = dn; }
        __syncthreads();

        if (t == 0) {
            float fdp = 0.f, fdn = 0.f;
            #pragma unroll
            for (int w = 0; w < BLOCK / 32; w++) { fdp += sm[0][w]; fdn += sm[1][w]; }

            const float d_pos = sqrtf(fdp) + EPSF;
            const float d_neg = sqrtf(fdn) + EPSF;

            const float lp = d_pos * d_pos;
            const float tn = fmaxf(MARGIN - d_neg, EPSF);
            local += (double)(lp + tn * tn);
        }
    }

    // --- block partial -> global accumulator; last block finalizes + resets ---
    if (t == 0) {
        atomicAdd(&g_acc, local);
        __threadfence();
        unsigned done = atomicAdd(&g_count, 1u);
        if (done == GRID - 1u) {
            // all blocks' atomics are visible (fence-before-count protocol)
            out[0] = (float)(g_acc / (2.0 * (double)N_SAMPLES));
            g_acc = 0.0;       // reset for next graph replay
            g_count = 0u;
            __threadfence();
        }
    }
}

extern "C" void kernel_launch(void* const* d_in, const int* in_sizes, int n_in,
                              void* d_out, int out_size)
{
    const float* emb = (const float*)d_in[0];
    // d_in[1] = labels (int32) — not needed by the loss itself
    const int*   pos = (const int*)d_in[2];
    const int*   neg = (const int*)d_in[3];
    float* out = (float*)d_out;

    cl_fused_kernel<<<GRID, BLOCK>>>(emb, pos, neg, out);
}

// round 5
// speedup vs baseline: 2.9045x; 2.9045x over previous
#include <cuda_runtime.h>

#define N_SAMPLES 16384
#define DIM       1024
#define MARGIN    1.0f
#define EPSF      1e-6f
#define BLOCK     256
#define WARPS     (BLOCK / 32)          // 8 samples per block
#define GRID      (N_SAMPLES / WARPS)   // 2048 blocks, one shot

__device__ double g_acc;      // zero-initialized at load; reset by last block
__device__ unsigned g_count;

__device__ __forceinline__ float dot4(float4 v) {
    return v.x*v.x + v.y*v.y + v.z*v.z + v.w*v.w;
}

__global__ __launch_bounds__(BLOCK)
void cl_warp_kernel(const float* __restrict__ emb,
                    const int* __restrict__ pos_idx,
                    const int* __restrict__ neg_idx,
                    float* __restrict__ out)
{
    const int wid  = threadIdx.x >> 5;
    const int lane = threadIdx.x & 31;
    const int i    = blockIdx.x * WARPS + wid;   // sample for this warp

    const int p = pos_idx[i];
    const int n = neg_idx[i];

    const float4* ra = (const float4*)(emb + (size_t)i * DIM);
    const float4* rb = (const float4*)(emb + (size_t)p * DIM);
    const float4* rc = (const float4*)(emb + (size_t)n * DIM);

    // 6 independent 128-bit loads -> MLP 6, all latency overlapped
    float4 a0 = ra[lane];      float4 a1 = ra[lane + 32];
    float4 b0 = rb[lane];      float4 b1 = rb[lane + 32];
    float4 c0 = rc[lane];      float4 c1 = rc[lane + 32];

    // --- phase 1: per-row sum of squares, warp-reduced (no barriers) ---
    float sa = dot4(a0) + dot4(a1);
    float sb = dot4(b0) + dot4(b1);
    float sc = dot4(c0) + dot4(c1);

    #pragma unroll
    for (int o = 16; o > 0; o >>= 1) {
        sa += __shfl_xor_sync(0xffffffffu, sa, o);
        sb += __shfl_xor_sync(0xffffffffu, sb, o);
        sc += __shfl_xor_sync(0xffffffffu, sc, o);
    }

    const float ia = 1.0f / fmaxf(sqrtf(sa), EPSF);
    const float ib = 1.0f / fmaxf(sqrtf(sb), EPSF);
    const float ic = 1.0f / fmaxf(sqrtf(sc), EPSF);

    // --- phase 2: squared "pairwise distance" sums (+eps inside the diff) ---
    float dp = 0.f, dn = 0.f;
    {
        float d;
        d = a0.x*ia - b0.x*ib + EPSF; dp += d*d;
        d = a0.y*ia - b0.y*ib + EPSF; dp += d*d;
        d = a0.z*ia - b0.z*ib + EPSF; dp += d*d;
        d = a0.w*ia - b0.w*ib + EPSF; dp += d*d;
        d = a1.x*ia - b1.x*ib + EPSF; dp += d*d;
        d = a1.y*ia - b1.y*ib + EPSF; dp += d*d;
        d = a1.z*ia - b1.z*ib + EPSF; dp += d*d;
        d = a1.w*ia - b1.w*ib + EPSF; dp += d*d;

        d = a0.x*ia - c0.x*ic + EPSF; dn += d*d;
        d = a0.y*ia - c0.y*ic + EPSF; dn += d*d;
        d = a0.z*ia - c0.z*ic + EPSF; dn += d*d;
        d = a0.w*ia - c0.w*ic + EPSF; dn += d*d;
        d = a1.x*ia - c1.x*ic + EPSF; dn += d*d;
        d = a1.y*ia - c1.y*ic + EPSF; dn += d*d;
        d = a1.z*ia - c1.z*ic + EPSF; dn += d*d;
        d = a1.w*ia - c1.w*ic + EPSF; dn += d*d;
    }

    #pragma unroll
    for (int o = 16; o > 0; o >>= 1) {
        dp += __shfl_xor_sync(0xffffffffu, dp, o);
        dn += __shfl_xor_sync(0xffffffffu, dn, o);
    }

    // --- per-warp loss -> smem; one barrier; one global atomic per block ---
    __shared__ double warp_loss[WARPS];
    if (lane == 0) {
        const float d_pos = sqrtf(dp) + EPSF;   // pairwise_distance + module eps
        const float d_neg = sqrtf(dn) + EPSF;
        const float tn = fmaxf(MARGIN - d_neg, EPSF);
        warp_loss[wid] = (double)(d_pos * d_pos + tn * tn);
    }
    __syncthreads();

    if (threadIdx.x == 0) {
        double blk = 0.0;
        #pragma unroll
        for (int w = 0; w < WARPS; w++) blk += warp_loss[w];

        atomicAdd(&g_acc, blk);
        __threadfence();
        unsigned done = atomicAdd(&g_count, 1u);
        if (done == GRID - 1u) {
            out[0] = (float)(g_acc / (2.0 * (double)N_SAMPLES));
            g_acc = 0.0;      // reset for next graph replay
            g_count = 0u;
            __threadfence();
        }
    }
}

extern "C" void kernel_launch(void* const* d_in, const int* in_sizes, int n_in,
                              void* d_out, int out_size)
{
    const float* emb = (const float*)d_in[0];
    // d_in[1] = labels (int32) — unused by the loss
    const int*   pos = (const int*)d_in[2];
    const int*   neg = (const int*)d_in[3];
    float* out = (float*)d_out;

    cl_warp_kernel<<<GRID, BLOCK>>>(emb, pos, neg, out);
}